// round 11
// baseline (speedup 1.0000x reference)
#include <cuda_runtime.h>
#include <cuda_fp16.h>
#include <math.h>

#define MAXN 50000
#define MAXE 1700000
#define HID 128
#define NG 64
#define NC 10

// ---------------- static device scratch ----------------
__device__ int    g_degi[MAXN];
__device__ int    g_rowptr[MAXN + 1];
__device__ int    g_cursor[MAXN];
__device__ int    g_csr[MAXE];
__device__ float  g_dinv[MAXN];
__device__ __half g_h [(size_t)MAXN * HID];   // GEMM out * dinv[row], fp16
__device__ __half g_ah[(size_t)MAXN * HID];   // agg out (activation), fp16
__device__ float  g_pool[NG * HID];
__device__ float  g_cnt[NG];

// ---------------- degree histogram ----------------
__global__ void hist_kernel(const int* __restrict__ dst, int* __restrict__ deg, int E) {
    int i = blockIdx.x * blockDim.x + threadIdx.x;
    if (i < E) atomicAdd(&deg[dst[i]], 1);
}

// ---------------- single-block scan: rowptr + cursor + dinv in one pass ----------------
__global__ __launch_bounds__(1024) void scan_kernel(
    const int* __restrict__ deg, int* __restrict__ rowptr,
    int* __restrict__ cursor, float* __restrict__ dinv, int N)
{
    const int T = 1024;
    int t = threadIdx.x;
    int C = (N + T - 1) / T;
    int lo = t * C;
    int hi = min(lo + C, N);
    if (lo > N) lo = N;
    if (hi < lo) hi = lo;

    int s = 0;
    for (int i = lo; i < hi; i++) s += deg[i];

    int lane = t & 31, wid = t >> 5;
    int v = s;
    #pragma unroll
    for (int o = 1; o < 32; o <<= 1) {
        int u = __shfl_up_sync(0xffffffffu, v, o);
        if (lane >= o) v += u;
    }
    __shared__ int wsum[32];
    if (lane == 31) wsum[wid] = v;
    __syncthreads();
    if (wid == 0) {
        int w = wsum[lane];
        #pragma unroll
        for (int o = 1; o < 32; o <<= 1) {
            int u = __shfl_up_sync(0xffffffffu, w, o);
            if (lane >= o) w += u;
        }
        wsum[lane] = w;
    }
    __syncthreads();
    int excl = v - s + (wid > 0 ? wsum[wid - 1] : 0);

    int run = excl;
    for (int i = lo; i < hi; i++) {
        int d = deg[i];
        rowptr[i] = run;
        cursor[i] = run;
        dinv[i] = rsqrtf((float)d + 1.0f);
        run += d;
    }
    if (hi == N) rowptr[N] = run;
}

// ---------------- CSR fill ----------------
__global__ void fill_kernel(const int* __restrict__ src, const int* __restrict__ dst,
                            int* __restrict__ cursor, int* __restrict__ csr, int E)
{
    int i = blockIdx.x * blockDim.x + threadIdx.x;
    if (i < E) {
        int d = dst[i];
        int p = atomicAdd(&cursor[d], 1);
        csr[p] = src[i];
    }
}

// ---------------- Tensor-core GEMM: C[M,128] = half((A @ W) * dinv[row]) ----------------
// As: row-major [m][k], Bs: n-major [n][k]  -> both fragment loads are vector LDS.32.
#define APAD 136

template<bool A_FP32>
__global__ __launch_bounds__(256) void hgemm128(
    const void* __restrict__ Aptr, const float* __restrict__ W,
    const float* __restrict__ dinv, __half* __restrict__ C, int M)
{
    extern __shared__ __half sm[];
    __half* As = sm;                 // [128 m][APAD k]
    __half* Bs = sm + 128 * APAD;    // [128 n][APAD k]

    const int tid = threadIdx.x;
    const int rowBase = blockIdx.x * 128;

    // ---- load A tile ----
    #pragma unroll
    for (int i = tid; i < 4096; i += 256) {
        int r = i >> 5;
        int c = (i & 31) * 4;
        int gr = rowBase + r;
        if (A_FP32) {
            float4 v = make_float4(0.f, 0.f, 0.f, 0.f);
            if (gr < M)
                v = *reinterpret_cast<const float4*>((const float*)Aptr + (size_t)gr * 128 + c);
            *reinterpret_cast<__half2*>(&As[r * APAD + c])     = __floats2half2_rn(v.x, v.y);
            *reinterpret_cast<__half2*>(&As[r * APAD + c + 2]) = __floats2half2_rn(v.z, v.w);
        } else {
            uint2 v = make_uint2(0u, 0u);
            if (gr < M)
                v = *reinterpret_cast<const uint2*>((const __half*)Aptr + (size_t)gr * 128 + c);
            *reinterpret_cast<uint2*>(&As[r * APAD + c]) = v;
        }
    }
    // ---- load W transposed into n-major Bs: Bs[n][k] = W[k][n] ----
    #pragma unroll
    for (int i = tid; i < 4096; i += 256) {
        int r = i >> 5;            // k row of W
        int c = (i & 31) * 4;      // n cols c..c+3
        float4 v = *reinterpret_cast<const float4*>(W + (size_t)r * 128 + c);
        Bs[(c + 0) * APAD + r] = __float2half_rn(v.x);
        Bs[(c + 1) * APAD + r] = __float2half_rn(v.y);
        Bs[(c + 2) * APAD + r] = __float2half_rn(v.z);
        Bs[(c + 3) * APAD + r] = __float2half_rn(v.w);
    }
    __syncthreads();

    const int wid  = tid >> 5;
    const int lane = tid & 31;
    const int m0 = (wid & 1) * 64;
    const int n0 = (wid >> 1) * 32;
    const int g = lane >> 2;
    const int t = lane & 3;

    float acc[4][4][4];
    #pragma unroll
    for (int mi = 0; mi < 4; mi++)
        #pragma unroll
        for (int ni = 0; ni < 4; ni++)
            #pragma unroll
            for (int q = 0; q < 4; q++) acc[mi][ni][q] = 0.f;

    #pragma unroll
    for (int ks = 0; ks < 8; ks++) {
        const int k0 = ks * 16;
        unsigned afr[4][4];
        #pragma unroll
        for (int mi = 0; mi < 4; mi++) {
            int ra = m0 + mi * 16;
            afr[mi][0] = *reinterpret_cast<const unsigned*>(&As[(ra + g)     * APAD + k0 + 2 * t]);
            afr[mi][1] = *reinterpret_cast<const unsigned*>(&As[(ra + 8 + g) * APAD + k0 + 2 * t]);
            afr[mi][2] = *reinterpret_cast<const unsigned*>(&As[(ra + g)     * APAD + k0 + 8 + 2 * t]);
            afr[mi][3] = *reinterpret_cast<const unsigned*>(&As[(ra + 8 + g) * APAD + k0 + 8 + 2 * t]);
        }
        unsigned bfr[4][2];
        #pragma unroll
        for (int ni = 0; ni < 4; ni++) {
            int col = n0 + ni * 8 + g;
            bfr[ni][0] = *reinterpret_cast<const unsigned*>(&Bs[col * APAD + k0 + 2 * t]);
            bfr[ni][1] = *reinterpret_cast<const unsigned*>(&Bs[col * APAD + k0 + 8 + 2 * t]);
        }
        #pragma unroll
        for (int mi = 0; mi < 4; mi++)
            #pragma unroll
            for (int ni = 0; ni < 4; ni++) {
                asm volatile(
                    "mma.sync.aligned.m16n8k16.row.col.f32.f16.f16.f32 "
                    "{%0,%1,%2,%3}, {%4,%5,%6,%7}, {%8,%9}, {%0,%1,%2,%3};\n"
                    : "+f"(acc[mi][ni][0]), "+f"(acc[mi][ni][1]),
                      "+f"(acc[mi][ni][2]), "+f"(acc[mi][ni][3])
                    : "r"(afr[mi][0]), "r"(afr[mi][1]), "r"(afr[mi][2]), "r"(afr[mi][3]),
                      "r"(bfr[ni][0]), "r"(bfr[ni][1]));
            }
    }

    #pragma unroll
    for (int mi = 0; mi < 4; mi++) {
        int r1 = rowBase + m0 + mi * 16 + g;
        int r2 = r1 + 8;
        float s1 = (r1 < M) ? __ldg(dinv + r1) : 0.f;
        float s2 = (r2 < M) ? __ldg(dinv + r2) : 0.f;
        #pragma unroll
        for (int ni = 0; ni < 4; ni++) {
            int col = n0 + ni * 8 + 2 * t;
            if (r1 < M)
                *reinterpret_cast<__half2*>(C + (size_t)r1 * 128 + col) =
                    __floats2half2_rn(acc[mi][ni][0] * s1, acc[mi][ni][1] * s1);
            if (r2 < M)
                *reinterpret_cast<__half2*>(C + (size_t)r2 * 128 + col) =
                    __floats2half2_rn(acc[mi][ni][2] * s2, acc[mi][ni][3] * s2);
        }
    }
}

// ---------------- pull-mode aggregation (R6 winner): 1 node/warp, LDG.64/lane ----------------
// out[d] = relu( dinv[d] * (hs[d] + sum_{s in N(d)} hs[s]) + bias )
__global__ __launch_bounds__(256) void agg_kernel(
    const __half* __restrict__ hs, const int* __restrict__ csr,
    const int* __restrict__ rowptr, const float* __restrict__ dinv,
    const float* __restrict__ bias, __half* __restrict__ out, int N)
{
    int w = (blockIdx.x * blockDim.x + threadIdx.x) >> 5;
    if (w >= N) return;
    int lane = threadIdx.x & 31;

    const uint2* hsv = reinterpret_cast<const uint2*>(hs);  // row = 32 uint2
    int start = __ldg(rowptr + w);
    int end   = __ldg(rowptr + w + 1);

    float acc0, acc1, acc2, acc3;
    {   // self loop
        uint2 u = hsv[(size_t)w * 32 + lane];
        float2 fa = __half22float2(*reinterpret_cast<__half2*>(&u.x));
        float2 fb = __half22float2(*reinterpret_cast<__half2*>(&u.y));
        acc0 = fa.x; acc1 = fa.y; acc2 = fb.x; acc3 = fb.y;
    }

    int j = start;
    for (; j + 4 <= end; j += 4) {
        int s0 = __ldg(csr + j);
        int s1 = __ldg(csr + j + 1);
        int s2 = __ldg(csr + j + 2);
        int s3 = __ldg(csr + j + 3);
        uint2 u0 = hsv[(size_t)s0 * 32 + lane];
        uint2 u1 = hsv[(size_t)s1 * 32 + lane];
        uint2 u2 = hsv[(size_t)s2 * 32 + lane];
        uint2 u3 = hsv[(size_t)s3 * 32 + lane];
        float2 a0 = __half22float2(*reinterpret_cast<__half2*>(&u0.x));
        float2 b0 = __half22float2(*reinterpret_cast<__half2*>(&u0.y));
        float2 a1 = __half22float2(*reinterpret_cast<__half2*>(&u1.x));
        float2 b1 = __half22float2(*reinterpret_cast<__half2*>(&u1.y));
        float2 a2 = __half22float2(*reinterpret_cast<__half2*>(&u2.x));
        float2 b2 = __half22float2(*reinterpret_cast<__half2*>(&u2.y));
        float2 a3 = __half22float2(*reinterpret_cast<__half2*>(&u3.x));
        float2 b3 = __half22float2(*reinterpret_cast<__half2*>(&u3.y));
        acc0 += (a0.x + a1.x) + (a2.x + a3.x);
        acc1 += (a0.y + a1.y) + (a2.y + a3.y);
        acc2 += (b0.x + b1.x) + (b2.x + b3.x);
        acc3 += (b0.y + b1.y) + (b2.y + b3.y);
    }
    for (; j < end; j++) {
        int s = __ldg(csr + j);
        uint2 u = hsv[(size_t)s * 32 + lane];
        float2 fa = __half22float2(*reinterpret_cast<__half2*>(&u.x));
        float2 fb = __half22float2(*reinterpret_cast<__half2*>(&u.y));
        acc0 += fa.x; acc1 += fa.y; acc2 += fb.x; acc3 += fb.y;
    }

    float di = __ldg(dinv + w);
    float4 bv = reinterpret_cast<const float4*>(bias)[lane];
    float r0 = fmaxf(fmaf(acc0, di, bv.x), 0.f);
    float r1 = fmaxf(fmaf(acc1, di, bv.y), 0.f);
    float r2 = fmaxf(fmaf(acc2, di, bv.z), 0.f);
    float r3 = fmaxf(fmaf(acc3, di, bv.w), 0.f);
    __half2 h0 = __floats2half2_rn(r0, r1);
    __half2 h1 = __floats2half2_rn(r2, r3);
    uint2 packed;
    packed.x = *reinterpret_cast<unsigned*>(&h0);
    packed.y = *reinterpret_cast<unsigned*>(&h1);
    reinterpret_cast<uint2*>(out)[(size_t)w * 32 + lane] = packed;
}

// ---------------- pooling over sorted batch ids (fp16 input) ----------------
#define POOL_ROWS 512
__global__ void pool_kernel(
    const __half* __restrict__ a, const int* __restrict__ batch,
    float* __restrict__ g, float* __restrict__ cnt, int N)
{
    int c = threadIdx.x;
    int row0 = blockIdx.x * POOL_ROWS;
    if (row0 >= N) return;
    int row1 = min(row0 + POOL_ROWS, N);

    int cur = __ldg(batch + row0);
    float acc = 0.f, count = 0.f;
    for (int r = row0; r < row1; r++) {
        int b = __ldg(batch + r);
        if (b != cur) {
            atomicAdd(&g[cur * HID + c], acc);
            if (c == 0) atomicAdd(&cnt[cur], count);
            acc = 0.f; count = 0.f; cur = b;
        }
        acc += __half2float(__ldg(a + (size_t)r * HID + c));
        count += 1.f;
    }
    atomicAdd(&g[cur * HID + c], acc);
    if (c == 0) atomicAdd(&cnt[cur], count);
}

// ---------------- final MLP ----------------
__global__ void mlp_kernel(
    const float* __restrict__ g, const float* __restrict__ cnt,
    const float* __restrict__ Wc1, const float* __restrict__ bc1,
    const float* __restrict__ Wc2, const float* __restrict__ bc2,
    float* __restrict__ out)
{
    __shared__ float gr[HID], z[HID];
    int b = blockIdx.x;
    int t = threadIdx.x;
    float c = cnt[b];
    c = (c < 1.f) ? 1.f : c;
    gr[t] = g[b * HID + t] / c;
    __syncthreads();

    float acc = bc1[t];
    for (int k = 0; k < HID; k++) acc += gr[k] * Wc1[k * HID + t];
    z[t] = fmaxf(acc, 0.f);
    __syncthreads();

    if (t < NC) {
        float o = bc2[t];
        for (int k = 0; k < HID; k++) o += z[k] * Wc2[k * NC + t];
        out[b * NC + t] = o;
    }
}

// ---------------- launch ----------------
extern "C" void kernel_launch(void* const* d_in, const int* in_sizes, int n_in,
                              void* d_out, int out_size)
{
    const float* x    = (const float*)d_in[0];
    const int*   edge = (const int*)  d_in[1];
    const int*   batc = (const int*)  d_in[2];
    const float* W1   = (const float*)d_in[3];
    const float* b1   = (const float*)d_in[4];
    const float* W2   = (const float*)d_in[5];
    const float* b2   = (const float*)d_in[6];
    const float* Wc1  = (const float*)d_in[7];
    const float* bc1  = (const float*)d_in[8];
    const float* Wc2  = (const float*)d_in[9];
    const float* bc2  = (const float*)d_in[10];

    const int N = in_sizes[0] / HID;
    const int E = in_sizes[1] / 2;
    const int* src = edge;
    const int* dst = edge + E;

    int *degi_p, *rowptr_p, *cursor_p, *csr_p;
    float *dinv_p, *g_p, *cnt_p;
    __half *h_p, *ah_p;
    cudaGetSymbolAddress((void**)&degi_p,   g_degi);
    cudaGetSymbolAddress((void**)&rowptr_p, g_rowptr);
    cudaGetSymbolAddress((void**)&cursor_p, g_cursor);
    cudaGetSymbolAddress((void**)&csr_p,    g_csr);
    cudaGetSymbolAddress((void**)&dinv_p,   g_dinv);
    cudaGetSymbolAddress((void**)&h_p,      g_h);
    cudaGetSymbolAddress((void**)&ah_p,     g_ah);
    cudaGetSymbolAddress((void**)&g_p,      g_pool);
    cudaGetSymbolAddress((void**)&cnt_p,    g_cnt);

    const int SMEM = 2 * 128 * APAD * (int)sizeof(__half);
    cudaFuncSetAttribute(hgemm128<true>,  cudaFuncAttributeMaxDynamicSharedMemorySize, SMEM);
    cudaFuncSetAttribute(hgemm128<false>, cudaFuncAttributeMaxDynamicSharedMemorySize, SMEM);

    // ---- CSR build + normalization (scan also writes cursor + dinv) ----
    cudaMemsetAsync(degi_p, 0, N * sizeof(int));
    hist_kernel<<<(E + 255) / 256, 256>>>(dst, degi_p, E);
    scan_kernel<<<1, 1024>>>(degi_p, rowptr_p, cursor_p, dinv_p, N);
    fill_kernel<<<(E + 255) / 256, 256>>>(src, dst, cursor_p, csr_p, E);

    const int gemmGrid = (N + 127) / 128;
    const int aggGrid  = (N * 32 + 255) / 256;

    // ---- layer 1 (agg1 is the 6th launch -> captured by ncu -s 5) ----
    hgemm128<true><<<gemmGrid, 256, SMEM>>>(x, W1, dinv_p, h_p, N);
    agg_kernel<<<aggGrid, 256>>>(h_p, csr_p, rowptr_p, dinv_p, b1, ah_p, N);

    // ---- layer 2 ----
    hgemm128<false><<<gemmGrid, 256, SMEM>>>(ah_p, W2, dinv_p, h_p, N);
    agg_kernel<<<aggGrid, 256>>>(h_p, csr_p, rowptr_p, dinv_p, b2, ah_p, N);

    // ---- pooling + MLP ----
    cudaMemsetAsync(g_p, 0, NG * HID * sizeof(float));
    cudaMemsetAsync(cnt_p, 0, NG * sizeof(float));
    pool_kernel<<<(N + POOL_ROWS - 1) / POOL_ROWS, HID>>>(ah_p, batc, g_p, cnt_p, N);
    mlp_kernel<<<NG, HID>>>(g_p, cnt_p, Wc1, bc1, Wc2, bc2, (float*)d_out);
}

// round 13
// speedup vs baseline: 1.0618x; 1.0618x over previous
#include <cuda_runtime.h>
#include <cuda_fp16.h>
#include <math.h>

#define MAXN 50000
#define MAXE 1700000
#define HID 128
#define NG 64
#define NC 10

// ---------------- static device scratch ----------------
__device__ int    g_degi[MAXN];
__device__ int    g_rowptr[MAXN + 1];
__device__ int    g_cursor[MAXN];
__device__ int    g_csr[MAXE];
__device__ float  g_dinv[MAXN];
__device__ __half g_h [(size_t)MAXN * HID];   // GEMM out * dinv[row], fp16
__device__ __half g_ah[(size_t)MAXN * HID];   // agg out (activation), fp16
__device__ float  g_pool[NG * HID];
__device__ float  g_cnt[NG];

// ---------------- degree histogram ----------------
__global__ void hist_kernel(const int* __restrict__ dst, int* __restrict__ deg, int E) {
    int i = blockIdx.x * blockDim.x + threadIdx.x;
    if (i < E) atomicAdd(&deg[dst[i]], 1);
}

// ---------------- single-block scan: rowptr + cursor + dinv in one pass ----------------
__global__ __launch_bounds__(1024) void scan_kernel(
    const int* __restrict__ deg, int* __restrict__ rowptr,
    int* __restrict__ cursor, float* __restrict__ dinv, int N)
{
    const int T = 1024;
    int t = threadIdx.x;
    int C = (N + T - 1) / T;
    int lo = t * C;
    int hi = min(lo + C, N);
    if (lo > N) lo = N;
    if (hi < lo) hi = lo;

    int s = 0;
    for (int i = lo; i < hi; i++) s += deg[i];

    int lane = t & 31, wid = t >> 5;
    int v = s;
    #pragma unroll
    for (int o = 1; o < 32; o <<= 1) {
        int u = __shfl_up_sync(0xffffffffu, v, o);
        if (lane >= o) v += u;
    }
    __shared__ int wsum[32];
    if (lane == 31) wsum[wid] = v;
    __syncthreads();
    if (wid == 0) {
        int w = wsum[lane];
        #pragma unroll
        for (int o = 1; o < 32; o <<= 1) {
            int u = __shfl_up_sync(0xffffffffu, w, o);
            if (lane >= o) w += u;
        }
        wsum[lane] = w;
    }
    __syncthreads();
    int excl = v - s + (wid > 0 ? wsum[wid - 1] : 0);

    int run = excl;
    for (int i = lo; i < hi; i++) {
        int d = deg[i];
        rowptr[i] = run;
        cursor[i] = run;
        dinv[i] = rsqrtf((float)d + 1.0f);
        run += d;
    }
    if (hi == N) rowptr[N] = run;
}

// ---------------- CSR fill ----------------
__global__ void fill_kernel(const int* __restrict__ src, const int* __restrict__ dst,
                            int* __restrict__ cursor, int* __restrict__ csr, int E)
{
    int i = blockIdx.x * blockDim.x + threadIdx.x;
    if (i < E) {
        int d = dst[i];
        int p = atomicAdd(&cursor[d], 1);
        csr[p] = src[i];
    }
}

// ---------------- Tensor-core GEMM (R4 proven version, 18.1us): k-major Bs ----------------
#define APAD 136

template<bool A_FP32>
__global__ __launch_bounds__(256) void hgemm128(
    const void* __restrict__ Aptr, const float* __restrict__ W,
    const float* __restrict__ dinv, __half* __restrict__ C, int M)
{
    extern __shared__ __half sm[];
    __half* As = sm;                 // [128][APAD]
    __half* Bs = sm + 128 * APAD;    // [128][APAD]  (k-major: Bs[k][n])

    const int tid = threadIdx.x;
    const int rowBase = blockIdx.x * 128;

    #pragma unroll
    for (int i = tid; i < 4096; i += 256) {
        int r = i >> 5;
        int c = (i & 31) * 4;
        int gr = rowBase + r;
        if (A_FP32) {
            float4 v = make_float4(0.f, 0.f, 0.f, 0.f);
            if (gr < M)
                v = *reinterpret_cast<const float4*>((const float*)Aptr + (size_t)gr * 128 + c);
            *reinterpret_cast<__half2*>(&As[r * APAD + c])     = __floats2half2_rn(v.x, v.y);
            *reinterpret_cast<__half2*>(&As[r * APAD + c + 2]) = __floats2half2_rn(v.z, v.w);
        } else {
            uint2 v = make_uint2(0u, 0u);
            if (gr < M)
                v = *reinterpret_cast<const uint2*>((const __half*)Aptr + (size_t)gr * 128 + c);
            *reinterpret_cast<uint2*>(&As[r * APAD + c]) = v;
        }
    }
    #pragma unroll
    for (int i = tid; i < 4096; i += 256) {
        int r = i >> 5;
        int c = (i & 31) * 4;
        float4 v = *reinterpret_cast<const float4*>(W + (size_t)r * 128 + c);
        *reinterpret_cast<__half2*>(&Bs[r * APAD + c])     = __floats2half2_rn(v.x, v.y);
        *reinterpret_cast<__half2*>(&Bs[r * APAD + c + 2]) = __floats2half2_rn(v.z, v.w);
    }
    __syncthreads();

    const int wid  = tid >> 5;
    const int lane = tid & 31;
    const int m0 = (wid & 1) * 64;
    const int n0 = (wid >> 1) * 32;
    const int g = lane >> 2;
    const int t = lane & 3;

    float acc[4][4][4];
    #pragma unroll
    for (int mi = 0; mi < 4; mi++)
        #pragma unroll
        for (int ni = 0; ni < 4; ni++)
            #pragma unroll
            for (int q = 0; q < 4; q++) acc[mi][ni][q] = 0.f;

    #pragma unroll
    for (int ks = 0; ks < 8; ks++) {
        const int k0 = ks * 16;
        unsigned afr[4][4];
        #pragma unroll
        for (int mi = 0; mi < 4; mi++) {
            int ra = m0 + mi * 16;
            afr[mi][0] = *reinterpret_cast<const unsigned*>(&As[(ra + g)     * APAD + k0 + 2 * t]);
            afr[mi][1] = *reinterpret_cast<const unsigned*>(&As[(ra + 8 + g) * APAD + k0 + 2 * t]);
            afr[mi][2] = *reinterpret_cast<const unsigned*>(&As[(ra + g)     * APAD + k0 + 8 + 2 * t]);
            afr[mi][3] = *reinterpret_cast<const unsigned*>(&As[(ra + 8 + g) * APAD + k0 + 8 + 2 * t]);
        }
        unsigned bfr[4][2];
        #pragma unroll
        for (int ni = 0; ni < 4; ni++) {
            int col = n0 + ni * 8 + g;
            __half2 p0 = __halves2half2(Bs[(k0 + 2 * t)     * APAD + col],
                                        Bs[(k0 + 2 * t + 1) * APAD + col]);
            __half2 p1 = __halves2half2(Bs[(k0 + 8 + 2 * t) * APAD + col],
                                        Bs[(k0 + 9 + 2 * t) * APAD + col]);
            bfr[ni][0] = *reinterpret_cast<unsigned*>(&p0);
            bfr[ni][1] = *reinterpret_cast<unsigned*>(&p1);
        }
        #pragma unroll
        for (int mi = 0; mi < 4; mi++)
            #pragma unroll
            for (int ni = 0; ni < 4; ni++) {
                asm volatile(
                    "mma.sync.aligned.m16n8k16.row.col.f32.f16.f16.f32 "
                    "{%0,%1,%2,%3}, {%4,%5,%6,%7}, {%8,%9}, {%0,%1,%2,%3};\n"
                    : "+f"(acc[mi][ni][0]), "+f"(acc[mi][ni][1]),
                      "+f"(acc[mi][ni][2]), "+f"(acc[mi][ni][3])
                    : "r"(afr[mi][0]), "r"(afr[mi][1]), "r"(afr[mi][2]), "r"(afr[mi][3]),
                      "r"(bfr[ni][0]), "r"(bfr[ni][1]));
            }
    }

    #pragma unroll
    for (int mi = 0; mi < 4; mi++) {
        int r1 = rowBase + m0 + mi * 16 + g;
        int r2 = r1 + 8;
        float s1 = (r1 < M) ? __ldg(dinv + r1) : 0.f;
        float s2 = (r2 < M) ? __ldg(dinv + r2) : 0.f;
        #pragma unroll
        for (int ni = 0; ni < 4; ni++) {
            int col = n0 + ni * 8 + 2 * t;
            if (r1 < M)
                *reinterpret_cast<__half2*>(C + (size_t)r1 * 128 + col) =
                    __floats2half2_rn(acc[mi][ni][0] * s1, acc[mi][ni][1] * s1);
            if (r2 < M)
                *reinterpret_cast<__half2*>(C + (size_t)r2 * 128 + col) =
                    __floats2half2_rn(acc[mi][ni][2] * s2, acc[mi][ni][3] * s2);
        }
    }
}

// ---------------- pull-mode aggregation: 1 node/warp, LDG.64/lane, unroll 8 ----------------
// out[d] = relu( dinv[d] * (hs[d] + sum_{s in N(d)} hs[s]) + bias )
__device__ __forceinline__ void acc_u2(const uint2& u, float& a0, float& a1, float& a2, float& a3) {
    float2 fa = __half22float2(*reinterpret_cast<const __half2*>(&u.x));
    float2 fb = __half22float2(*reinterpret_cast<const __half2*>(&u.y));
    a0 += fa.x; a1 += fa.y; a2 += fb.x; a3 += fb.y;
}

__global__ __launch_bounds__(256) void agg_kernel(
    const __half* __restrict__ hs, const int* __restrict__ csr,
    const int* __restrict__ rowptr, const float* __restrict__ dinv,
    const float* __restrict__ bias, __half* __restrict__ out, int N)
{
    int w = (blockIdx.x * blockDim.x + threadIdx.x) >> 5;
    if (w >= N) return;
    int lane = threadIdx.x & 31;

    const uint2* hsv = reinterpret_cast<const uint2*>(hs);  // row = 32 uint2
    int start = __ldg(rowptr + w);
    int end   = __ldg(rowptr + w + 1);

    float acc0, acc1, acc2, acc3;
    {   // self loop
        uint2 u = hsv[(size_t)w * 32 + lane];
        float2 fa = __half22float2(*reinterpret_cast<__half2*>(&u.x));
        float2 fb = __half22float2(*reinterpret_cast<__half2*>(&u.y));
        acc0 = fa.x; acc1 = fa.y; acc2 = fb.x; acc3 = fb.y;
    }

    int j = start;
    for (; j + 8 <= end; j += 8) {
        int s[8];
        #pragma unroll
        for (int q = 0; q < 8; q++) s[q] = __ldg(csr + j + q);
        uint2 u[8];
        #pragma unroll
        for (int q = 0; q < 8; q++) u[q] = hsv[(size_t)s[q] * 32 + lane];
        #pragma unroll
        for (int q = 0; q < 8; q++) acc_u2(u[q], acc0, acc1, acc2, acc3);
    }
    if (j + 4 <= end) {
        int s[4];
        #pragma unroll
        for (int q = 0; q < 4; q++) s[q] = __ldg(csr + j + q);
        uint2 u[4];
        #pragma unroll
        for (int q = 0; q < 4; q++) u[q] = hsv[(size_t)s[q] * 32 + lane];
        #pragma unroll
        for (int q = 0; q < 4; q++) acc_u2(u[q], acc0, acc1, acc2, acc3);
        j += 4;
    }
    for (; j < end; j++) {
        int s = __ldg(csr + j);
        uint2 u = hsv[(size_t)s * 32 + lane];
        acc_u2(u, acc0, acc1, acc2, acc3);
    }

    float di = __ldg(dinv + w);
    float4 bv = reinterpret_cast<const float4*>(bias)[lane];
    float r0 = fmaxf(fmaf(acc0, di, bv.x), 0.f);
    float r1 = fmaxf(fmaf(acc1, di, bv.y), 0.f);
    float r2 = fmaxf(fmaf(acc2, di, bv.z), 0.f);
    float r3 = fmaxf(fmaf(acc3, di, bv.w), 0.f);
    __half2 h0 = __floats2half2_rn(r0, r1);
    __half2 h1 = __floats2half2_rn(r2, r3);
    uint2 packed;
    packed.x = *reinterpret_cast<unsigned*>(&h0);
    packed.y = *reinterpret_cast<unsigned*>(&h1);
    reinterpret_cast<uint2*>(out)[(size_t)w * 32 + lane] = packed;
}

// ---------------- pooling over sorted batch ids (fp16 input) ----------------
#define POOL_ROWS 512
__global__ void pool_kernel(
    const __half* __restrict__ a, const int* __restrict__ batch,
    float* __restrict__ g, float* __restrict__ cnt, int N)
{
    int c = threadIdx.x;
    int row0 = blockIdx.x * POOL_ROWS;
    if (row0 >= N) return;
    int row1 = min(row0 + POOL_ROWS, N);

    int cur = __ldg(batch + row0);
    float acc = 0.f, count = 0.f;
    for (int r = row0; r < row1; r++) {
        int b = __ldg(batch + r);
        if (b != cur) {
            atomicAdd(&g[cur * HID + c], acc);
            if (c == 0) atomicAdd(&cnt[cur], count);
            acc = 0.f; count = 0.f; cur = b;
        }
        acc += __half2float(__ldg(a + (size_t)r * HID + c));
        count += 1.f;
    }
    atomicAdd(&g[cur * HID + c], acc);
    if (c == 0) atomicAdd(&cnt[cur], count);
}

// ---------------- final MLP ----------------
__global__ void mlp_kernel(
    const float* __restrict__ g, const float* __restrict__ cnt,
    const float* __restrict__ Wc1, const float* __restrict__ bc1,
    const float* __restrict__ Wc2, const float* __restrict__ bc2,
    float* __restrict__ out)
{
    __shared__ float gr[HID], z[HID];
    int b = blockIdx.x;
    int t = threadIdx.x;
    float c = cnt[b];
    c = (c < 1.f) ? 1.f : c;
    gr[t] = g[b * HID + t] / c;
    __syncthreads();

    float acc = bc1[t];
    for (int k = 0; k < HID; k++) acc += gr[k] * Wc1[k * HID + t];
    z[t] = fmaxf(acc, 0.f);
    __syncthreads();

    if (t < NC) {
        float o = bc2[t];
        for (int k = 0; k < HID; k++) o += z[k] * Wc2[k * NC + t];
        out[b * NC + t] = o;
    }
}

// ---------------- launch ----------------
extern "C" void kernel_launch(void* const* d_in, const int* in_sizes, int n_in,
                              void* d_out, int out_size)
{
    const float* x    = (const float*)d_in[0];
    const int*   edge = (const int*)  d_in[1];
    const int*   batc = (const int*)  d_in[2];
    const float* W1   = (const float*)d_in[3];
    const float* b1   = (const float*)d_in[4];
    const float* W2   = (const float*)d_in[5];
    const float* b2   = (const float*)d_in[6];
    const float* Wc1  = (const float*)d_in[7];
    const float* bc1  = (const float*)d_in[8];
    const float* Wc2  = (const float*)d_in[9];
    const float* bc2  = (const float*)d_in[10];

    const int N = in_sizes[0] / HID;
    const int E = in_sizes[1] / 2;
    const int* src = edge;
    const int* dst = edge + E;

    int *degi_p, *rowptr_p, *cursor_p, *csr_p;
    float *dinv_p, *g_p, *cnt_p;
    __half *h_p, *ah_p;
    cudaGetSymbolAddress((void**)&degi_p,   g_degi);
    cudaGetSymbolAddress((void**)&rowptr_p, g_rowptr);
    cudaGetSymbolAddress((void**)&cursor_p, g_cursor);
    cudaGetSymbolAddress((void**)&csr_p,    g_csr);
    cudaGetSymbolAddress((void**)&dinv_p,   g_dinv);
    cudaGetSymbolAddress((void**)&h_p,      g_h);
    cudaGetSymbolAddress((void**)&ah_p,     g_ah);
    cudaGetSymbolAddress((void**)&g_p,      g_pool);
    cudaGetSymbolAddress((void**)&cnt_p,    g_cnt);

    const int SMEM = 2 * 128 * APAD * (int)sizeof(__half);
    cudaFuncSetAttribute(hgemm128<true>,  cudaFuncAttributeMaxDynamicSharedMemorySize, SMEM);
    cudaFuncSetAttribute(hgemm128<false>, cudaFuncAttributeMaxDynamicSharedMemorySize, SMEM);

    // ---- CSR build + normalization ----
    cudaMemsetAsync(degi_p, 0, N * sizeof(int));
    hist_kernel<<<(E + 255) / 256, 256>>>(dst, degi_p, E);           // kernel 1
    scan_kernel<<<1, 1024>>>(degi_p, rowptr_p, cursor_p, dinv_p, N); // kernel 2
    fill_kernel<<<(E + 255) / 256, 256>>>(src, dst, cursor_p, csr_p, E); // kernel 3

    const int gemmGrid = (N + 127) / 128;
    const int aggGrid  = (N * 32 + 255) / 256;

    // ---- DIAGNOSTIC: agg on first N/4 nodes as kernel #4 (ncu captures 4th kernel).
    // Deterministic (reads csr/rowptr + g_h, which is 0 on first call and the fixed
    // gemm2 output on replays); its output is fully overwritten by the real agg below.
    const int Nd = N / 4;
    agg_kernel<<<(Nd * 32 + 255) / 256, 256>>>(h_p, csr_p, rowptr_p, dinv_p, b1, ah_p, Nd); // kernel 4

    // ---- layer 1 ----
    hgemm128<true><<<gemmGrid, 256, SMEM>>>(x, W1, dinv_p, h_p, N);
    agg_kernel<<<aggGrid, 256>>>(h_p, csr_p, rowptr_p, dinv_p, b1, ah_p, N);

    // ---- layer 2 ----
    hgemm128<false><<<gemmGrid, 256, SMEM>>>(ah_p, W2, dinv_p, h_p, N);
    agg_kernel<<<aggGrid, 256>>>(h_p, csr_p, rowptr_p, dinv_p, b2, ah_p, N);

    // ---- pooling + MLP ----
    cudaMemsetAsync(g_p, 0, NG * HID * sizeof(float));
    cudaMemsetAsync(cnt_p, 0, NG * sizeof(float));
    pool_kernel<<<(N + POOL_ROWS - 1) / POOL_ROWS, HID>>>(ah_p, batc, g_p, cnt_p, N);
    mlp_kernel<<<NG, HID>>>(g_p, cnt_p, Wc1, bc1, Wc2, bc2, (float*)d_out);
}

// round 14
// speedup vs baseline: 1.1142x; 1.0494x over previous
#include <cuda_runtime.h>
#include <cuda_fp16.h>
#include <math.h>

#define MAXN 50000
#define MAXE 1700000
#define HID 128
#define NG 64
#define NC 10

// ---------------- static device scratch ----------------
__device__ int    g_degi[MAXN];
__device__ int    g_rowptr[MAXN + 1];
__device__ int    g_cursor[MAXN];
__device__ int    g_csr[MAXE];
__device__ float  g_dinv[MAXN];
__device__ __half g_h [(size_t)MAXN * HID];   // GEMM out * dinv[row], fp16
__device__ __half g_ah[(size_t)MAXN * HID];   // agg out (activation), fp16
__device__ float  g_pool[NG * HID];
__device__ float  g_cnt[NG];

// ---------------- degree histogram ----------------
__global__ void hist_kernel(const int* __restrict__ dst, int* __restrict__ deg, int E) {
    int i = blockIdx.x * blockDim.x + threadIdx.x;
    if (i < E) atomicAdd(&deg[dst[i]], 1);
}

// ---------------- single-block scan: rowptr + cursor + dinv in one pass ----------------
__global__ __launch_bounds__(1024) void scan_kernel(
    const int* __restrict__ deg, int* __restrict__ rowptr,
    int* __restrict__ cursor, float* __restrict__ dinv, int N)
{
    const int T = 1024;
    int t = threadIdx.x;
    int C = (N + T - 1) / T;
    int lo = t * C;
    int hi = min(lo + C, N);
    if (lo > N) lo = N;
    if (hi < lo) hi = lo;

    int s = 0;
    for (int i = lo; i < hi; i++) s += deg[i];

    int lane = t & 31, wid = t >> 5;
    int v = s;
    #pragma unroll
    for (int o = 1; o < 32; o <<= 1) {
        int u = __shfl_up_sync(0xffffffffu, v, o);
        if (lane >= o) v += u;
    }
    __shared__ int wsum[32];
    if (lane == 31) wsum[wid] = v;
    __syncthreads();
    if (wid == 0) {
        int w = wsum[lane];
        #pragma unroll
        for (int o = 1; o < 32; o <<= 1) {
            int u = __shfl_up_sync(0xffffffffu, w, o);
            if (lane >= o) w += u;
        }
        wsum[lane] = w;
    }
    __syncthreads();
    int excl = v - s + (wid > 0 ? wsum[wid - 1] : 0);

    int run = excl;
    for (int i = lo; i < hi; i++) {
        int d = deg[i];
        rowptr[i] = run;
        cursor[i] = run;
        dinv[i] = rsqrtf((float)d + 1.0f);
        run += d;
    }
    if (hi == N) rowptr[N] = run;
}

// ---------------- CSR fill ----------------
__global__ void fill_kernel(const int* __restrict__ src, const int* __restrict__ dst,
                            int* __restrict__ cursor, int* __restrict__ csr, int E)
{
    int i = blockIdx.x * blockDim.x + threadIdx.x;
    if (i < E) {
        int d = dst[i];
        int p = atomicAdd(&cursor[d], 1);
        csr[p] = src[i];
    }
}

// ---------------- Tensor-core GEMM (R4 proven version, 18.1us): k-major Bs ----------------
#define APAD 136

template<bool A_FP32>
__global__ __launch_bounds__(256) void hgemm128(
    const void* __restrict__ Aptr, const float* __restrict__ W,
    const float* __restrict__ dinv, __half* __restrict__ C, int M)
{
    extern __shared__ __half sm[];
    __half* As = sm;                 // [128][APAD]
    __half* Bs = sm + 128 * APAD;    // [128][APAD]  (k-major: Bs[k][n])

    const int tid = threadIdx.x;
    const int rowBase = blockIdx.x * 128;

    #pragma unroll
    for (int i = tid; i < 4096; i += 256) {
        int r = i >> 5;
        int c = (i & 31) * 4;
        int gr = rowBase + r;
        if (A_FP32) {
            float4 v = make_float4(0.f, 0.f, 0.f, 0.f);
            if (gr < M)
                v = *reinterpret_cast<const float4*>((const float*)Aptr + (size_t)gr * 128 + c);
            *reinterpret_cast<__half2*>(&As[r * APAD + c])     = __floats2half2_rn(v.x, v.y);
            *reinterpret_cast<__half2*>(&As[r * APAD + c + 2]) = __floats2half2_rn(v.z, v.w);
        } else {
            uint2 v = make_uint2(0u, 0u);
            if (gr < M)
                v = *reinterpret_cast<const uint2*>((const __half*)Aptr + (size_t)gr * 128 + c);
            *reinterpret_cast<uint2*>(&As[r * APAD + c]) = v;
        }
    }
    #pragma unroll
    for (int i = tid; i < 4096; i += 256) {
        int r = i >> 5;
        int c = (i & 31) * 4;
        float4 v = *reinterpret_cast<const float4*>(W + (size_t)r * 128 + c);
        *reinterpret_cast<__half2*>(&Bs[r * APAD + c])     = __floats2half2_rn(v.x, v.y);
        *reinterpret_cast<__half2*>(&Bs[r * APAD + c + 2]) = __floats2half2_rn(v.z, v.w);
    }
    __syncthreads();

    const int wid  = tid >> 5;
    const int lane = tid & 31;
    const int m0 = (wid & 1) * 64;
    const int n0 = (wid >> 1) * 32;
    const int g = lane >> 2;
    const int t = lane & 3;

    float acc[4][4][4];
    #pragma unroll
    for (int mi = 0; mi < 4; mi++)
        #pragma unroll
        for (int ni = 0; ni < 4; ni++)
            #pragma unroll
            for (int q = 0; q < 4; q++) acc[mi][ni][q] = 0.f;

    #pragma unroll
    for (int ks = 0; ks < 8; ks++) {
        const int k0 = ks * 16;
        unsigned afr[4][4];
        #pragma unroll
        for (int mi = 0; mi < 4; mi++) {
            int ra = m0 + mi * 16;
            afr[mi][0] = *reinterpret_cast<const unsigned*>(&As[(ra + g)     * APAD + k0 + 2 * t]);
            afr[mi][1] = *reinterpret_cast<const unsigned*>(&As[(ra + 8 + g) * APAD + k0 + 2 * t]);
            afr[mi][2] = *reinterpret_cast<const unsigned*>(&As[(ra + g)     * APAD + k0 + 8 + 2 * t]);
            afr[mi][3] = *reinterpret_cast<const unsigned*>(&As[(ra + 8 + g) * APAD + k0 + 8 + 2 * t]);
        }
        unsigned bfr[4][2];
        #pragma unroll
        for (int ni = 0; ni < 4; ni++) {
            int col = n0 + ni * 8 + g;
            __half2 p0 = __halves2half2(Bs[(k0 + 2 * t)     * APAD + col],
                                        Bs[(k0 + 2 * t + 1) * APAD + col]);
            __half2 p1 = __halves2half2(Bs[(k0 + 8 + 2 * t) * APAD + col],
                                        Bs[(k0 + 9 + 2 * t) * APAD + col]);
            bfr[ni][0] = *reinterpret_cast<unsigned*>(&p0);
            bfr[ni][1] = *reinterpret_cast<unsigned*>(&p1);
        }
        #pragma unroll
        for (int mi = 0; mi < 4; mi++)
            #pragma unroll
            for (int ni = 0; ni < 4; ni++) {
                asm volatile(
                    "mma.sync.aligned.m16n8k16.row.col.f32.f16.f16.f32 "
                    "{%0,%1,%2,%3}, {%4,%5,%6,%7}, {%8,%9}, {%0,%1,%2,%3};\n"
                    : "+f"(acc[mi][ni][0]), "+f"(acc[mi][ni][1]),
                      "+f"(acc[mi][ni][2]), "+f"(acc[mi][ni][3])
                    : "r"(afr[mi][0]), "r"(afr[mi][1]), "r"(afr[mi][2]), "r"(afr[mi][3]),
                      "r"(bfr[ni][0]), "r"(bfr[ni][1]));
            }
    }

    #pragma unroll
    for (int mi = 0; mi < 4; mi++) {
        int r1 = rowBase + m0 + mi * 16 + g;
        int r2 = r1 + 8;
        float s1 = (r1 < M) ? __ldg(dinv + r1) : 0.f;
        float s2 = (r2 < M) ? __ldg(dinv + r2) : 0.f;
        #pragma unroll
        for (int ni = 0; ni < 4; ni++) {
            int col = n0 + ni * 8 + 2 * t;
            if (r1 < M)
                *reinterpret_cast<__half2*>(C + (size_t)r1 * 128 + col) =
                    __floats2half2_rn(acc[mi][ni][0] * s1, acc[mi][ni][1] * s1);
            if (r2 < M)
                *reinterpret_cast<__half2*>(C + (size_t)r2 * 128 + col) =
                    __floats2half2_rn(acc[mi][ni][2] * s2, acc[mi][ni][3] * s2);
        }
    }
}

// ---------------- aggregation: 2 nodes/warp (R6 winner) + HADD2 group accumulation ----------
// out[d] = relu( dinv[d] * (hs[d] + sum_{s in N(d)} hs[s]) + bias )
// Lanes 0-15 -> node 2*warp, lanes 16-31 -> node 2*warp+1. Lane owns 8 features (uint4).
// Neighbor rows accumulated in __half2 within 16-edge groups, flushed to fp32 between groups.
__global__ __launch_bounds__(256) void agg_kernel(
    const __half* __restrict__ hs, const int* __restrict__ csr,
    const int* __restrict__ rowptr, const float* __restrict__ dinv,
    const float* __restrict__ bias, __half* __restrict__ out, int N)
{
    int warp = (blockIdx.x * blockDim.x + threadIdx.x) >> 5;
    int lane = threadIdx.x & 31;
    int half = lane >> 4;
    int hl   = lane & 15;
    int w = warp * 2 + half;
    if (w >= N) return;

    const uint4* hsv = reinterpret_cast<const uint4*>(hs);   // row = 16 uint4

    int start = __ldg(rowptr + w);
    int end   = __ldg(rowptr + w + 1);

    float f[8];
    {   // self loop (fp32)
        uint4 u = hsv[(size_t)w * 16 + hl];
        float2 q0 = __half22float2(*reinterpret_cast<__half2*>(&u.x));
        float2 q1 = __half22float2(*reinterpret_cast<__half2*>(&u.y));
        float2 q2 = __half22float2(*reinterpret_cast<__half2*>(&u.z));
        float2 q3 = __half22float2(*reinterpret_cast<__half2*>(&u.w));
        f[0] = q0.x; f[1] = q0.y; f[2] = q1.x; f[3] = q1.y;
        f[4] = q2.x; f[5] = q2.y; f[6] = q3.x; f[7] = q3.y;
    }

    int j = start;
    while (j < end) {
        int stop = min(end, j + 16);
        __half2 a0 = __floats2half2_rn(0.f, 0.f);
        __half2 a1 = a0, a2 = a0, a3 = a0;

        for (; j + 4 <= stop; j += 4) {
            int s0 = __ldg(csr + j);
            int s1 = __ldg(csr + j + 1);
            int s2 = __ldg(csr + j + 2);
            int s3 = __ldg(csr + j + 3);
            uint4 u0 = hsv[(size_t)s0 * 16 + hl];
            uint4 u1 = hsv[(size_t)s1 * 16 + hl];
            uint4 u2 = hsv[(size_t)s2 * 16 + hl];
            uint4 u3 = hsv[(size_t)s3 * 16 + hl];
            a0 = __hadd2(a0, __hadd2(__hadd2(*reinterpret_cast<__half2*>(&u0.x),
                                             *reinterpret_cast<__half2*>(&u1.x)),
                                     __hadd2(*reinterpret_cast<__half2*>(&u2.x),
                                             *reinterpret_cast<__half2*>(&u3.x))));
            a1 = __hadd2(a1, __hadd2(__hadd2(*reinterpret_cast<__half2*>(&u0.y),
                                             *reinterpret_cast<__half2*>(&u1.y)),
                                     __hadd2(*reinterpret_cast<__half2*>(&u2.y),
                                             *reinterpret_cast<__half2*>(&u3.y))));
            a2 = __hadd2(a2, __hadd2(__hadd2(*reinterpret_cast<__half2*>(&u0.z),
                                             *reinterpret_cast<__half2*>(&u1.z)),
                                     __hadd2(*reinterpret_cast<__half2*>(&u2.z),
                                             *reinterpret_cast<__half2*>(&u3.z))));
            a3 = __hadd2(a3, __hadd2(__hadd2(*reinterpret_cast<__half2*>(&u0.w),
                                             *reinterpret_cast<__half2*>(&u1.w)),
                                     __hadd2(*reinterpret_cast<__half2*>(&u2.w),
                                             *reinterpret_cast<__half2*>(&u3.w))));
        }
        for (; j < stop; j++) {
            int s = __ldg(csr + j);
            uint4 u = hsv[(size_t)s * 16 + hl];
            a0 = __hadd2(a0, *reinterpret_cast<__half2*>(&u.x));
            a1 = __hadd2(a1, *reinterpret_cast<__half2*>(&u.y));
            a2 = __hadd2(a2, *reinterpret_cast<__half2*>(&u.z));
            a3 = __hadd2(a3, *reinterpret_cast<__half2*>(&u.w));
        }
        // flush group to fp32
        float2 q0 = __half22float2(a0);
        float2 q1 = __half22float2(a1);
        float2 q2 = __half22float2(a2);
        float2 q3 = __half22float2(a3);
        f[0] += q0.x; f[1] += q0.y; f[2] += q1.x; f[3] += q1.y;
        f[4] += q2.x; f[5] += q2.y; f[6] += q3.x; f[7] += q3.y;
    }

    float di = __ldg(dinv + w);
    const float4* b4 = reinterpret_cast<const float4*>(bias);
    float4 bv0 = b4[hl * 2];
    float4 bv1 = b4[hl * 2 + 1];
    float r0 = fmaxf(fmaf(f[0], di, bv0.x), 0.f);
    float r1 = fmaxf(fmaf(f[1], di, bv0.y), 0.f);
    float r2 = fmaxf(fmaf(f[2], di, bv0.z), 0.f);
    float r3 = fmaxf(fmaf(f[3], di, bv0.w), 0.f);
    float r4 = fmaxf(fmaf(f[4], di, bv1.x), 0.f);
    float r5 = fmaxf(fmaf(f[5], di, bv1.y), 0.f);
    float r6 = fmaxf(fmaf(f[6], di, bv1.z), 0.f);
    float r7 = fmaxf(fmaf(f[7], di, bv1.w), 0.f);
    __half2 h0 = __floats2half2_rn(r0, r1);
    __half2 h1 = __floats2half2_rn(r2, r3);
    __half2 h2 = __floats2half2_rn(r4, r5);
    __half2 h3 = __floats2half2_rn(r6, r7);
    uint4 packed;
    packed.x = *reinterpret_cast<unsigned*>(&h0);
    packed.y = *reinterpret_cast<unsigned*>(&h1);
    packed.z = *reinterpret_cast<unsigned*>(&h2);
    packed.w = *reinterpret_cast<unsigned*>(&h3);
    reinterpret_cast<uint4*>(out)[(size_t)w * 16 + hl] = packed;
}

// ---------------- pooling over sorted batch ids (fp16 input) ----------------
#define POOL_ROWS 512
__global__ void pool_kernel(
    const __half* __restrict__ a, const int* __restrict__ batch,
    float* __restrict__ g, float* __restrict__ cnt, int N)
{
    int c = threadIdx.x;
    int row0 = blockIdx.x * POOL_ROWS;
    if (row0 >= N) return;
    int row1 = min(row0 + POOL_ROWS, N);

    int cur = __ldg(batch + row0);
    float acc = 0.f, count = 0.f;
    for (int r = row0; r < row1; r++) {
        int b = __ldg(batch + r);
        if (b != cur) {
            atomicAdd(&g[cur * HID + c], acc);
            if (c == 0) atomicAdd(&cnt[cur], count);
            acc = 0.f; count = 0.f; cur = b;
        }
        acc += __half2float(__ldg(a + (size_t)r * HID + c));
        count += 1.f;
    }
    atomicAdd(&g[cur * HID + c], acc);
    if (c == 0) atomicAdd(&cnt[cur], count);
}

// ---------------- final MLP ----------------
__global__ void mlp_kernel(
    const float* __restrict__ g, const float* __restrict__ cnt,
    const float* __restrict__ Wc1, const float* __restrict__ bc1,
    const float* __restrict__ Wc2, const float* __restrict__ bc2,
    float* __restrict__ out)
{
    __shared__ float gr[HID], z[HID];
    int b = blockIdx.x;
    int t = threadIdx.x;
    float c = cnt[b];
    c = (c < 1.f) ? 1.f : c;
    gr[t] = g[b * HID + t] / c;
    __syncthreads();

    float acc = bc1[t];
    for (int k = 0; k < HID; k++) acc += gr[k] * Wc1[k * HID + t];
    z[t] = fmaxf(acc, 0.f);
    __syncthreads();

    if (t < NC) {
        float o = bc2[t];
        for (int k = 0; k < HID; k++) o += z[k] * Wc2[k * NC + t];
        out[b * NC + t] = o;
    }
}

// ---------------- launch ----------------
extern "C" void kernel_launch(void* const* d_in, const int* in_sizes, int n_in,
                              void* d_out, int out_size)
{
    const float* x    = (const float*)d_in[0];
    const int*   edge = (const int*)  d_in[1];
    const int*   batc = (const int*)  d_in[2];
    const float* W1   = (const float*)d_in[3];
    const float* b1   = (const float*)d_in[4];
    const float* W2   = (const float*)d_in[5];
    const float* b2   = (const float*)d_in[6];
    const float* Wc1  = (const float*)d_in[7];
    const float* bc1  = (const float*)d_in[8];
    const float* Wc2  = (const float*)d_in[9];
    const float* bc2  = (const float*)d_in[10];

    const int N = in_sizes[0] / HID;
    const int E = in_sizes[1] / 2;
    const int* src = edge;
    const int* dst = edge + E;

    int *degi_p, *rowptr_p, *cursor_p, *csr_p;
    float *dinv_p, *g_p, *cnt_p;
    __half *h_p, *ah_p;
    cudaGetSymbolAddress((void**)&degi_p,   g_degi);
    cudaGetSymbolAddress((void**)&rowptr_p, g_rowptr);
    cudaGetSymbolAddress((void**)&cursor_p, g_cursor);
    cudaGetSymbolAddress((void**)&csr_p,    g_csr);
    cudaGetSymbolAddress((void**)&dinv_p,   g_dinv);
    cudaGetSymbolAddress((void**)&h_p,      g_h);
    cudaGetSymbolAddress((void**)&ah_p,     g_ah);
    cudaGetSymbolAddress((void**)&g_p,      g_pool);
    cudaGetSymbolAddress((void**)&cnt_p,    g_cnt);

    const int SMEM = 2 * 128 * APAD * (int)sizeof(__half);
    cudaFuncSetAttribute(hgemm128<true>,  cudaFuncAttributeMaxDynamicSharedMemorySize, SMEM);
    cudaFuncSetAttribute(hgemm128<false>, cudaFuncAttributeMaxDynamicSharedMemorySize, SMEM);

    // ---- CSR build + normalization ----
    cudaMemsetAsync(degi_p, 0, N * sizeof(int));
    hist_kernel<<<(E + 255) / 256, 256>>>(dst, degi_p, E);
    scan_kernel<<<1, 1024>>>(degi_p, rowptr_p, cursor_p, dinv_p, N);
    fill_kernel<<<(E + 255) / 256, 256>>>(src, dst, cursor_p, csr_p, E);

    const int gemmGrid = (N + 127) / 128;
    const int aggGrid  = (((N + 1) / 2) * 32 + 255) / 256;

    // ---- layer 1 ----
    hgemm128<true><<<gemmGrid, 256, SMEM>>>(x, W1, dinv_p, h_p, N);
    agg_kernel<<<aggGrid, 256>>>(h_p, csr_p, rowptr_p, dinv_p, b1, ah_p, N);

    // ---- layer 2 ----
    hgemm128<false><<<gemmGrid, 256, SMEM>>>(ah_p, W2, dinv_p, h_p, N);
    agg_kernel<<<aggGrid, 256>>>(h_p, csr_p, rowptr_p, dinv_p, b2, ah_p, N);

    // ---- pooling + MLP ----
    cudaMemsetAsync(g_p, 0, NG * HID * sizeof(float));
    cudaMemsetAsync(cnt_p, 0, NG * sizeof(float));
    pool_kernel<<<(N + POOL_ROWS - 1) / POOL_ROWS, HID>>>(ah_p, batc, g_p, cnt_p, N);
    mlp_kernel<<<NG, HID>>>(g_p, cnt_p, Wc1, bc1, Wc2, bc2, (float*)d_out);
}

// round 15
// speedup vs baseline: 1.3379x; 1.2008x over previous
#include <cuda_runtime.h>
#include <cuda_fp16.h>
#include <math.h>

#define MAXN 50000
#define MAXE 1700000
#define HID 128
#define NG 64
#define NC 10

// ---------------- static device scratch ----------------
__device__ int    g_degi[MAXN];
__device__ int    g_rowptr[MAXN + 1];
__device__ int    g_cursor[MAXN];
__device__ int    g_csr[MAXE];
__device__ float  g_dinv[MAXN];
__device__ __half g_h [(size_t)MAXN * HID];   // GEMM out * dinv[row], fp16
__device__ __half g_ah[(size_t)MAXN * HID];   // agg out (activation), fp16
__device__ float  g_pool[NG * HID];
__device__ float  g_cnt[NG];

// ---------------- degree histogram ----------------
__global__ void hist_kernel(const int* __restrict__ dst, int* __restrict__ deg, int E) {
    int i = blockIdx.x * blockDim.x + threadIdx.x;
    if (i < E) atomicAdd(&deg[dst[i]], 1);
}

// ---------------- single-block exclusive scan (rowptr ONLY — keep it light) ----------------
__global__ __launch_bounds__(1024) void scan_kernel(
    const int* __restrict__ deg, int* __restrict__ rowptr, int N)
{
    const int T = 1024;
    int t = threadIdx.x;
    int C = (N + T - 1) / T;
    int lo = t * C;
    int hi = min(lo + C, N);
    if (lo > N) lo = N;
    if (hi < lo) hi = lo;

    int s = 0;
    for (int i = lo; i < hi; i++) s += deg[i];

    int lane = t & 31, wid = t >> 5;
    int v = s;
    #pragma unroll
    for (int o = 1; o < 32; o <<= 1) {
        int u = __shfl_up_sync(0xffffffffu, v, o);
        if (lane >= o) v += u;
    }
    __shared__ int wsum[32];
    if (lane == 31) wsum[wid] = v;
    __syncthreads();
    if (wid == 0) {
        int w = wsum[lane];
        #pragma unroll
        for (int o = 1; o < 32; o <<= 1) {
            int u = __shfl_up_sync(0xffffffffu, w, o);
            if (lane >= o) w += u;
        }
        wsum[lane] = w;
    }
    __syncthreads();
    int excl = v - s + (wid > 0 ? wsum[wid - 1] : 0);

    int run = excl;
    for (int i = lo; i < hi; i++) { rowptr[i] = run; run += deg[i]; }
    if (hi == N) rowptr[N] = run;
}

// ---------------- CSR fill ----------------
__global__ void fill_kernel(const int* __restrict__ src, const int* __restrict__ dst,
                            int* __restrict__ cursor, int* __restrict__ csr, int E)
{
    int i = blockIdx.x * blockDim.x + threadIdx.x;
    if (i < E) {
        int d = dst[i];
        int p = atomicAdd(&cursor[d], 1);
        csr[p] = src[i];
    }
}

__global__ void dinv_kernel(const int* __restrict__ deg, float* __restrict__ dinv, int N) {
    int i = blockIdx.x * blockDim.x + threadIdx.x;
    if (i < N) dinv[i] = rsqrtf((float)deg[i] + 1.0f);
}

// ---------------- Tensor-core GEMM (proven 18.1us version): k-major Bs ----------------
#define APAD 136

template<bool A_FP32>
__global__ __launch_bounds__(256) void hgemm128(
    const void* __restrict__ Aptr, const float* __restrict__ W,
    const float* __restrict__ dinv, __half* __restrict__ C, int M)
{
    extern __shared__ __half sm[];
    __half* As = sm;                 // [128][APAD]
    __half* Bs = sm + 128 * APAD;    // [128][APAD]  (k-major: Bs[k][n])

    const int tid = threadIdx.x;
    const int rowBase = blockIdx.x * 128;

    #pragma unroll
    for (int i = tid; i < 4096; i += 256) {
        int r = i >> 5;
        int c = (i & 31) * 4;
        int gr = rowBase + r;
        if (A_FP32) {
            float4 v = make_float4(0.f, 0.f, 0.f, 0.f);
            if (gr < M)
                v = *reinterpret_cast<const float4*>((const float*)Aptr + (size_t)gr * 128 + c);
            *reinterpret_cast<__half2*>(&As[r * APAD + c])     = __floats2half2_rn(v.x, v.y);
            *reinterpret_cast<__half2*>(&As[r * APAD + c + 2]) = __floats2half2_rn(v.z, v.w);
        } else {
            uint2 v = make_uint2(0u, 0u);
            if (gr < M)
                v = *reinterpret_cast<const uint2*>((const __half*)Aptr + (size_t)gr * 128 + c);
            *reinterpret_cast<uint2*>(&As[r * APAD + c]) = v;
        }
    }
    #pragma unroll
    for (int i = tid; i < 4096; i += 256) {
        int r = i >> 5;
        int c = (i & 31) * 4;
        float4 v = *reinterpret_cast<const float4*>(W + (size_t)r * 128 + c);
        *reinterpret_cast<__half2*>(&Bs[r * APAD + c])     = __floats2half2_rn(v.x, v.y);
        *reinterpret_cast<__half2*>(&Bs[r * APAD + c + 2]) = __floats2half2_rn(v.z, v.w);
    }
    __syncthreads();

    const int wid  = tid >> 5;
    const int lane = tid & 31;
    const int m0 = (wid & 1) * 64;
    const int n0 = (wid >> 1) * 32;
    const int g = lane >> 2;
    const int t = lane & 3;

    float acc[4][4][4];
    #pragma unroll
    for (int mi = 0; mi < 4; mi++)
        #pragma unroll
        for (int ni = 0; ni < 4; ni++)
            #pragma unroll
            for (int q = 0; q < 4; q++) acc[mi][ni][q] = 0.f;

    #pragma unroll
    for (int ks = 0; ks < 8; ks++) {
        const int k0 = ks * 16;
        unsigned afr[4][4];
        #pragma unroll
        for (int mi = 0; mi < 4; mi++) {
            int ra = m0 + mi * 16;
            afr[mi][0] = *reinterpret_cast<const unsigned*>(&As[(ra + g)     * APAD + k0 + 2 * t]);
            afr[mi][1] = *reinterpret_cast<const unsigned*>(&As[(ra + 8 + g) * APAD + k0 + 2 * t]);
            afr[mi][2] = *reinterpret_cast<const unsigned*>(&As[(ra + g)     * APAD + k0 + 8 + 2 * t]);
            afr[mi][3] = *reinterpret_cast<const unsigned*>(&As[(ra + 8 + g) * APAD + k0 + 8 + 2 * t]);
        }
        unsigned bfr[4][2];
        #pragma unroll
        for (int ni = 0; ni < 4; ni++) {
            int col = n0 + ni * 8 + g;
            __half2 p0 = __halves2half2(Bs[(k0 + 2 * t)     * APAD + col],
                                        Bs[(k0 + 2 * t + 1) * APAD + col]);
            __half2 p1 = __halves2half2(Bs[(k0 + 8 + 2 * t) * APAD + col],
                                        Bs[(k0 + 9 + 2 * t) * APAD + col]);
            bfr[ni][0] = *reinterpret_cast<unsigned*>(&p0);
            bfr[ni][1] = *reinterpret_cast<unsigned*>(&p1);
        }
        #pragma unroll
        for (int mi = 0; mi < 4; mi++)
            #pragma unroll
            for (int ni = 0; ni < 4; ni++) {
                asm volatile(
                    "mma.sync.aligned.m16n8k16.row.col.f32.f16.f16.f32 "
                    "{%0,%1,%2,%3}, {%4,%5,%6,%7}, {%8,%9}, {%0,%1,%2,%3};\n"
                    : "+f"(acc[mi][ni][0]), "+f"(acc[mi][ni][1]),
                      "+f"(acc[mi][ni][2]), "+f"(acc[mi][ni][3])
                    : "r"(afr[mi][0]), "r"(afr[mi][1]), "r"(afr[mi][2]), "r"(afr[mi][3]),
                      "r"(bfr[ni][0]), "r"(bfr[ni][1]));
            }
    }

    #pragma unroll
    for (int mi = 0; mi < 4; mi++) {
        int r1 = rowBase + m0 + mi * 16 + g;
        int r2 = r1 + 8;
        float s1 = (r1 < M) ? __ldg(dinv + r1) : 0.f;
        float s2 = (r2 < M) ? __ldg(dinv + r2) : 0.f;
        #pragma unroll
        for (int ni = 0; ni < 4; ni++) {
            int col = n0 + ni * 8 + 2 * t;
            if (r1 < M)
                *reinterpret_cast<__half2*>(C + (size_t)r1 * 128 + col) =
                    __floats2half2_rn(acc[mi][ni][0] * s1, acc[mi][ni][1] * s1);
            if (r2 < M)
                *reinterpret_cast<__half2*>(C + (size_t)r2 * 128 + col) =
                    __floats2half2_rn(acc[mi][ni][2] * s2, acc[mi][ni][3] * s2);
        }
    }
}

// ---------------- aggregation: 1 node/warp (269us winner layout) + HADD2 groups ----------
// out[d] = relu( dinv[d] * (hs[d] + sum_{s in N(d)} hs[s]) + bias )
// Lane owns 4 features (uint2 = 2 half2). Neighbors summed in __half2 within
// 16-edge groups (HADD2 tree), flushed to fp32 between groups.
__global__ __launch_bounds__(256) void agg_kernel(
    const __half* __restrict__ hs, const int* __restrict__ csr,
    const int* __restrict__ rowptr, const float* __restrict__ dinv,
    const float* __restrict__ bias, __half* __restrict__ out, int N)
{
    int w = (blockIdx.x * blockDim.x + threadIdx.x) >> 5;
    if (w >= N) return;
    int lane = threadIdx.x & 31;

    const uint2* hsv = reinterpret_cast<const uint2*>(hs);  // row = 32 uint2
    int start = __ldg(rowptr + w);
    int end   = __ldg(rowptr + w + 1);

    float f0, f1, f2, f3;
    {   // self loop (fp32)
        uint2 u = hsv[(size_t)w * 32 + lane];
        float2 qa = __half22float2(*reinterpret_cast<__half2*>(&u.x));
        float2 qb = __half22float2(*reinterpret_cast<__half2*>(&u.y));
        f0 = qa.x; f1 = qa.y; f2 = qb.x; f3 = qb.y;
    }

    int j = start;
    while (j < end) {
        int stop = min(end, j + 16);
        __half2 a0 = __floats2half2_rn(0.f, 0.f);
        __half2 a1 = a0;

        for (; j + 4 <= stop; j += 4) {
            int s0 = __ldg(csr + j);
            int s1 = __ldg(csr + j + 1);
            int s2 = __ldg(csr + j + 2);
            int s3 = __ldg(csr + j + 3);
            uint2 u0 = hsv[(size_t)s0 * 32 + lane];
            uint2 u1 = hsv[(size_t)s1 * 32 + lane];
            uint2 u2 = hsv[(size_t)s2 * 32 + lane];
            uint2 u3 = hsv[(size_t)s3 * 32 + lane];
            __half2 px = __hadd2(*reinterpret_cast<__half2*>(&u0.x),
                                 *reinterpret_cast<__half2*>(&u1.x));
            __half2 qx = __hadd2(*reinterpret_cast<__half2*>(&u2.x),
                                 *reinterpret_cast<__half2*>(&u3.x));
            a0 = __hadd2(a0, __hadd2(px, qx));
            __half2 py = __hadd2(*reinterpret_cast<__half2*>(&u0.y),
                                 *reinterpret_cast<__half2*>(&u1.y));
            __half2 qy = __hadd2(*reinterpret_cast<__half2*>(&u2.y),
                                 *reinterpret_cast<__half2*>(&u3.y));
            a1 = __hadd2(a1, __hadd2(py, qy));
        }
        for (; j < stop; j++) {
            int s = __ldg(csr + j);
            uint2 u = hsv[(size_t)s * 32 + lane];
            a0 = __hadd2(a0, *reinterpret_cast<__half2*>(&u.x));
            a1 = __hadd2(a1, *reinterpret_cast<__half2*>(&u.y));
        }
        float2 qa = __half22float2(a0);
        float2 qb = __half22float2(a1);
        f0 += qa.x; f1 += qa.y; f2 += qb.x; f3 += qb.y;
    }

    float di = __ldg(dinv + w);
    float4 bv = reinterpret_cast<const float4*>(bias)[lane];
    float r0 = fmaxf(fmaf(f0, di, bv.x), 0.f);
    float r1 = fmaxf(fmaf(f1, di, bv.y), 0.f);
    float r2 = fmaxf(fmaf(f2, di, bv.z), 0.f);
    float r3 = fmaxf(fmaf(f3, di, bv.w), 0.f);
    __half2 h0 = __floats2half2_rn(r0, r1);
    __half2 h1 = __floats2half2_rn(r2, r3);
    uint2 packed;
    packed.x = *reinterpret_cast<unsigned*>(&h0);
    packed.y = *reinterpret_cast<unsigned*>(&h1);
    reinterpret_cast<uint2*>(out)[(size_t)w * 32 + lane] = packed;
}

// ---------------- pooling over sorted batch ids (fp16 input) ----------------
#define POOL_ROWS 512
__global__ void pool_kernel(
    const __half* __restrict__ a, const int* __restrict__ batch,
    float* __restrict__ g, float* __restrict__ cnt, int N)
{
    int c = threadIdx.x;
    int row0 = blockIdx.x * POOL_ROWS;
    if (row0 >= N) return;
    int row1 = min(row0 + POOL_ROWS, N);

    int cur = __ldg(batch + row0);
    float acc = 0.f, count = 0.f;
    for (int r = row0; r < row1; r++) {
        int b = __ldg(batch + r);
        if (b != cur) {
            atomicAdd(&g[cur * HID + c], acc);
            if (c == 0) atomicAdd(&cnt[cur], count);
            acc = 0.f; count = 0.f; cur = b;
        }
        acc += __half2float(__ldg(a + (size_t)r * HID + c));
        count += 1.f;
    }
    atomicAdd(&g[cur * HID + c], acc);
    if (c == 0) atomicAdd(&cnt[cur], count);
}

// ---------------- final MLP ----------------
__global__ void mlp_kernel(
    const float* __restrict__ g, const float* __restrict__ cnt,
    const float* __restrict__ Wc1, const float* __restrict__ bc1,
    const float* __restrict__ Wc2, const float* __restrict__ bc2,
    float* __restrict__ out)
{
    __shared__ float gr[HID], z[HID];
    int b = blockIdx.x;
    int t = threadIdx.x;
    float c = cnt[b];
    c = (c < 1.f) ? 1.f : c;
    gr[t] = g[b * HID + t] / c;
    __syncthreads();

    float acc = bc1[t];
    for (int k = 0; k < HID; k++) acc += gr[k] * Wc1[k * HID + t];
    z[t] = fmaxf(acc, 0.f);
    __syncthreads();

    if (t < NC) {
        float o = bc2[t];
        for (int k = 0; k < HID; k++) o += z[k] * Wc2[k * NC + t];
        out[b * NC + t] = o;
    }
}

// ---------------- launch (269us-proven structure) ----------------
extern "C" void kernel_launch(void* const* d_in, const int* in_sizes, int n_in,
                              void* d_out, int out_size)
{
    const float* x    = (const float*)d_in[0];
    const int*   edge = (const int*)  d_in[1];
    const int*   batc = (const int*)  d_in[2];
    const float* W1   = (const float*)d_in[3];
    const float* b1   = (const float*)d_in[4];
    const float* W2   = (const float*)d_in[5];
    const float* b2   = (const float*)d_in[6];
    const float* Wc1  = (const float*)d_in[7];
    const float* bc1  = (const float*)d_in[8];
    const float* Wc2  = (const float*)d_in[9];
    const float* bc2  = (const float*)d_in[10];

    const int N = in_sizes[0] / HID;
    const int E = in_sizes[1] / 2;
    const int* src = edge;
    const int* dst = edge + E;

    int *degi_p, *rowptr_p, *cursor_p, *csr_p;
    float *dinv_p, *g_p, *cnt_p;
    __half *h_p, *ah_p;
    cudaGetSymbolAddress((void**)&degi_p,   g_degi);
    cudaGetSymbolAddress((void**)&rowptr_p, g_rowptr);
    cudaGetSymbolAddress((void**)&cursor_p, g_cursor);
    cudaGetSymbolAddress((void**)&csr_p,    g_csr);
    cudaGetSymbolAddress((void**)&dinv_p,   g_dinv);
    cudaGetSymbolAddress((void**)&h_p,      g_h);
    cudaGetSymbolAddress((void**)&ah_p,     g_ah);
    cudaGetSymbolAddress((void**)&g_p,      g_pool);
    cudaGetSymbolAddress((void**)&cnt_p,    g_cnt);

    const int SMEM = 2 * 128 * APAD * (int)sizeof(__half);
    cudaFuncSetAttribute(hgemm128<true>,  cudaFuncAttributeMaxDynamicSharedMemorySize, SMEM);
    cudaFuncSetAttribute(hgemm128<false>, cudaFuncAttributeMaxDynamicSharedMemorySize, SMEM);

    // ---- CSR build + normalization (unfused: light single-block scan) ----
    cudaMemsetAsync(degi_p, 0, N * sizeof(int));
    hist_kernel<<<(E + 255) / 256, 256>>>(dst, degi_p, E);
    scan_kernel<<<1, 1024>>>(degi_p, rowptr_p, N);
    cudaMemcpyAsync(cursor_p, rowptr_p, N * sizeof(int), cudaMemcpyDeviceToDevice);
    fill_kernel<<<(E + 255) / 256, 256>>>(src, dst, cursor_p, csr_p, E);
    dinv_kernel<<<(N + 255) / 256, 256>>>(degi_p, dinv_p, N);

    const int gemmGrid = (N + 127) / 128;
    const int aggGrid  = (N * 32 + 255) / 256;

    // ---- layer 1 ----
    hgemm128<true><<<gemmGrid, 256, SMEM>>>(x, W1, dinv_p, h_p, N);
    agg_kernel<<<aggGrid, 256>>>(h_p, csr_p, rowptr_p, dinv_p, b1, ah_p, N);

    // ---- layer 2 ----
    hgemm128<false><<<gemmGrid, 256, SMEM>>>(ah_p, W2, dinv_p, h_p, N);
    agg_kernel<<<aggGrid, 256>>>(h_p, csr_p, rowptr_p, dinv_p, b2, ah_p, N);

    // ---- pooling + MLP ----
    cudaMemsetAsync(g_p, 0, NG * HID * sizeof(float));
    cudaMemsetAsync(cnt_p, 0, NG * sizeof(float));
    pool_kernel<<<(N + POOL_ROWS - 1) / POOL_ROWS, HID>>>(ah_p, batc, g_p, cnt_p, N);
    mlp_kernel<<<NG, HID>>>(g_p, cnt_p, Wc1, bc1, Wc2, bc2, (float*)d_out);
}

// round 17
// speedup vs baseline: 1.6366x; 1.2232x over previous
#include <cuda_runtime.h>
#include <cuda_fp16.h>
#include <math.h>

#define MAXN 50000
#define MAXE 1700000
#define HID 128
#define NG 64
#define NC 10

// ---------------- static device scratch ----------------
__device__ int    g_degi[MAXN];
__device__ int    g_rowptr[MAXN + 1];
__device__ int    g_cursor[MAXN];
__device__ int    g_csr[MAXE];
__device__ float  g_dinv[MAXN];
__device__ __half g_h [(size_t)MAXN * HID];   // GEMM out * dinv[row], fp16
__device__ __half g_ah[(size_t)MAXN * HID];   // agg out (activation), fp16
__device__ float  g_pool[NG * HID];
__device__ float  g_cnt[NG];

// ---------------- degree histogram ----------------
__global__ void hist_kernel(const int* __restrict__ dst, int* __restrict__ deg, int E) {
    int i = blockIdx.x * blockDim.x + threadIdx.x;
    if (i < E) atomicAdd(&deg[dst[i]], 1);
}

// ---------------- single-block exclusive scan (rowptr ONLY — keep it light) ----------------
__global__ __launch_bounds__(1024) void scan_kernel(
    const int* __restrict__ deg, int* __restrict__ rowptr, int N)
{
    const int T = 1024;
    int t = threadIdx.x;
    int C = (N + T - 1) / T;
    int lo = t * C;
    int hi = min(lo + C, N);
    if (lo > N) lo = N;
    if (hi < lo) hi = lo;

    int s = 0;
    for (int i = lo; i < hi; i++) s += deg[i];

    int lane = t & 31, wid = t >> 5;
    int v = s;
    #pragma unroll
    for (int o = 1; o < 32; o <<= 1) {
        int u = __shfl_up_sync(0xffffffffu, v, o);
        if (lane >= o) v += u;
    }
    __shared__ int wsum[32];
    if (lane == 31) wsum[wid] = v;
    __syncthreads();
    if (wid == 0) {
        int w = wsum[lane];
        #pragma unroll
        for (int o = 1; o < 32; o <<= 1) {
            int u = __shfl_up_sync(0xffffffffu, w, o);
            if (lane >= o) w += u;
        }
        wsum[lane] = w;
    }
    __syncthreads();
    int excl = v - s + (wid > 0 ? wsum[wid - 1] : 0);

    int run = excl;
    for (int i = lo; i < hi; i++) { rowptr[i] = run; run += deg[i]; }
    if (hi == N) rowptr[N] = run;
}

// ---------------- CSR fill ----------------
__global__ void fill_kernel(const int* __restrict__ src, const int* __restrict__ dst,
                            int* __restrict__ cursor, int* __restrict__ csr, int E)
{
    int i = blockIdx.x * blockDim.x + threadIdx.x;
    if (i < E) {
        int d = dst[i];
        int p = atomicAdd(&cursor[d], 1);
        csr[p] = src[i];
    }
}

__global__ void dinv_kernel(const int* __restrict__ deg, float* __restrict__ dinv, int N) {
    int i = blockIdx.x * blockDim.x + threadIdx.x;
    if (i < N) dinv[i] = rsqrtf((float)deg[i] + 1.0f);
}

// ---------------- Tensor-core GEMM: k-major Bs, 2 blocks/SM ----------------
#define APAD 136

template<bool A_FP32>
__global__ __launch_bounds__(256, 2) void hgemm128(
    const void* __restrict__ Aptr, const float* __restrict__ W,
    const float* __restrict__ dinv, __half* __restrict__ C, int M)
{
    extern __shared__ __half sm[];
    __half* As = sm;                 // [128][APAD]
    __half* Bs = sm + 128 * APAD;    // [128][APAD]  (k-major: Bs[k][n])

    const int tid = threadIdx.x;
    const int rowBase = blockIdx.x * 128;

    #pragma unroll
    for (int i = tid; i < 4096; i += 256) {
        int r = i >> 5;
        int c = (i & 31) * 4;
        int gr = rowBase + r;
        if (A_FP32) {
            float4 v = make_float4(0.f, 0.f, 0.f, 0.f);
            if (gr < M)
                v = *reinterpret_cast<const float4*>((const float*)Aptr + (size_t)gr * 128 + c);
            *reinterpret_cast<__half2*>(&As[r * APAD + c])     = __floats2half2_rn(v.x, v.y);
            *reinterpret_cast<__half2*>(&As[r * APAD + c + 2]) = __floats2half2_rn(v.z, v.w);
        } else {
            uint2 v = make_uint2(0u, 0u);
            if (gr < M)
                v = *reinterpret_cast<const uint2*>((const __half*)Aptr + (size_t)gr * 128 + c);
            *reinterpret_cast<uint2*>(&As[r * APAD + c]) = v;
        }
    }
    #pragma unroll
    for (int i = tid; i < 4096; i += 256) {
        int r = i >> 5;
        int c = (i & 31) * 4;
        float4 v = *reinterpret_cast<const float4*>(W + (size_t)r * 128 + c);
        *reinterpret_cast<__half2*>(&Bs[r * APAD + c])     = __floats2half2_rn(v.x, v.y);
        *reinterpret_cast<__half2*>(&Bs[r * APAD + c + 2]) = __floats2half2_rn(v.z, v.w);
    }
    __syncthreads();

    const int wid  = tid >> 5;
    const int lane = tid & 31;
    const int m0 = (wid & 1) * 64;
    const int n0 = (wid >> 1) * 32;
    const int g = lane >> 2;
    const int t = lane & 3;

    float acc[4][4][4];
    #pragma unroll
    for (int mi = 0; mi < 4; mi++)
        #pragma unroll
        for (int ni = 0; ni < 4; ni++)
            #pragma unroll
            for (int q = 0; q < 4; q++) acc[mi][ni][q] = 0.f;

    #pragma unroll
    for (int ks = 0; ks < 8; ks++) {
        const int k0 = ks * 16;
        unsigned afr[4][4];
        #pragma unroll
        for (int mi = 0; mi < 4; mi++) {
            int ra = m0 + mi * 16;
            afr[mi][0] = *reinterpret_cast<const unsigned*>(&As[(ra + g)     * APAD + k0 + 2 * t]);
            afr[mi][1] = *reinterpret_cast<const unsigned*>(&As[(ra + 8 + g) * APAD + k0 + 2 * t]);
            afr[mi][2] = *reinterpret_cast<const unsigned*>(&As[(ra + g)     * APAD + k0 + 8 + 2 * t]);
            afr[mi][3] = *reinterpret_cast<const unsigned*>(&As[(ra + 8 + g) * APAD + k0 + 8 + 2 * t]);
        }
        unsigned bfr[4][2];
        #pragma unroll
        for (int ni = 0; ni < 4; ni++) {
            int col = n0 + ni * 8 + g;
            __half2 p0 = __halves2half2(Bs[(k0 + 2 * t)     * APAD + col],
                                        Bs[(k0 + 2 * t + 1) * APAD + col]);
            __half2 p1 = __halves2half2(Bs[(k0 + 8 + 2 * t) * APAD + col],
                                        Bs[(k0 + 9 + 2 * t) * APAD + col]);
            bfr[ni][0] = *reinterpret_cast<unsigned*>(&p0);
            bfr[ni][1] = *reinterpret_cast<unsigned*>(&p1);
        }
        #pragma unroll
        for (int mi = 0; mi < 4; mi++)
            #pragma unroll
            for (int ni = 0; ni < 4; ni++) {
                asm volatile(
                    "mma.sync.aligned.m16n8k16.row.col.f32.f16.f16.f32 "
                    "{%0,%1,%2,%3}, {%4,%5,%6,%7}, {%8,%9}, {%0,%1,%2,%3};\n"
                    : "+f"(acc[mi][ni][0]), "+f"(acc[mi][ni][1]),
                      "+f"(acc[mi][ni][2]), "+f"(acc[mi][ni][3])
                    : "r"(afr[mi][0]), "r"(afr[mi][1]), "r"(afr[mi][2]), "r"(afr[mi][3]),
                      "r"(bfr[ni][0]), "r"(bfr[ni][1]));
            }
    }

    #pragma unroll
    for (int mi = 0; mi < 4; mi++) {
        int r1 = rowBase + m0 + mi * 16 + g;
        int r2 = r1 + 8;
        float s1 = (r1 < M) ? __ldg(dinv + r1) : 0.f;
        float s2 = (r2 < M) ? __ldg(dinv + r2) : 0.f;
        #pragma unroll
        for (int ni = 0; ni < 4; ni++) {
            int col = n0 + ni * 8 + 2 * t;
            if (r1 < M)
                *reinterpret_cast<__half2*>(C + (size_t)r1 * 128 + col) =
                    __floats2half2_rn(acc[mi][ni][0] * s1, acc[mi][ni][1] * s1);
            if (r2 < M)
                *reinterpret_cast<__half2*>(C + (size_t)r2 * 128 + col) =
                    __floats2half2_rn(acc[mi][ni][2] * s2, acc[mi][ni][3] * s2);
        }
    }
}

// ---------------- aggregation (252us winner): 1 node/warp + HADD2 groups ----------
__global__ __launch_bounds__(256) void agg_kernel(
    const __half* __restrict__ hs, const int* __restrict__ csr,
    const int* __restrict__ rowptr, const float* __restrict__ dinv,
    const float* __restrict__ bias, __half* __restrict__ out, int N)
{
    int w = (blockIdx.x * blockDim.x + threadIdx.x) >> 5;
    if (w >= N) return;
    int lane = threadIdx.x & 31;

    const uint2* hsv = reinterpret_cast<const uint2*>(hs);  // row = 32 uint2
    int start = __ldg(rowptr + w);
    int end   = __ldg(rowptr + w + 1);

    float f0, f1, f2, f3;
    {   // self loop (fp32)
        uint2 u = hsv[(size_t)w * 32 + lane];
        float2 qa = __half22float2(*reinterpret_cast<__half2*>(&u.x));
        float2 qb = __half22float2(*reinterpret_cast<__half2*>(&u.y));
        f0 = qa.x; f1 = qa.y; f2 = qb.x; f3 = qb.y;
    }

    int j = start;
    while (j < end) {
        int stop = min(end, j + 16);
        __half2 a0 = __floats2half2_rn(0.f, 0.f);
        __half2 a1 = a0;

        for (; j + 4 <= stop; j += 4) {
            int s0 = __ldg(csr + j);
            int s1 = __ldg(csr + j + 1);
            int s2 = __ldg(csr + j + 2);
            int s3 = __ldg(csr + j + 3);
            uint2 u0 = hsv[(size_t)s0 * 32 + lane];
            uint2 u1 = hsv[(size_t)s1 * 32 + lane];
            uint2 u2 = hsv[(size_t)s2 * 32 + lane];
            uint2 u3 = hsv[(size_t)s3 * 32 + lane];
            __half2 px = __hadd2(*reinterpret_cast<__half2*>(&u0.x),
                                 *reinterpret_cast<__half2*>(&u1.x));
            __half2 qx = __hadd2(*reinterpret_cast<__half2*>(&u2.x),
                                 *reinterpret_cast<__half2*>(&u3.x));
            a0 = __hadd2(a0, __hadd2(px, qx));
            __half2 py = __hadd2(*reinterpret_cast<__half2*>(&u0.y),
                                 *reinterpret_cast<__half2*>(&u1.y));
            __half2 qy = __hadd2(*reinterpret_cast<__half2*>(&u2.y),
                                 *reinterpret_cast<__half2*>(&u3.y));
            a1 = __hadd2(a1, __hadd2(py, qy));
        }
        for (; j < stop; j++) {
            int s = __ldg(csr + j);
            uint2 u = hsv[(size_t)s * 32 + lane];
            a0 = __hadd2(a0, *reinterpret_cast<__half2*>(&u.x));
            a1 = __hadd2(a1, *reinterpret_cast<__half2*>(&u.y));
        }
        float2 qa = __half22float2(a0);
        float2 qb = __half22float2(a1);
        f0 += qa.x; f1 += qa.y; f2 += qb.x; f3 += qb.y;
    }

    float di = __ldg(dinv + w);
    float4 bv = reinterpret_cast<const float4*>(bias)[lane];
    float r0 = fmaxf(fmaf(f0, di, bv.x), 0.f);
    float r1 = fmaxf(fmaf(f1, di, bv.y), 0.f);
    float r2 = fmaxf(fmaf(f2, di, bv.z), 0.f);
    float r3 = fmaxf(fmaf(f3, di, bv.w), 0.f);
    __half2 h0 = __floats2half2_rn(r0, r1);
    __half2 h1 = __floats2half2_rn(r2, r3);
    uint2 packed;
    packed.x = *reinterpret_cast<unsigned*>(&h0);
    packed.y = *reinterpret_cast<unsigned*>(&h1);
    reinterpret_cast<uint2*>(out)[(size_t)w * 32 + lane] = packed;
}

// ---------------- pooling: 32 lanes/row (uint2), 8 warps stride rows ----------------
#define POOL_ROWS 512
__global__ __launch_bounds__(256) void pool_kernel(
    const __half* __restrict__ a, const int* __restrict__ batch,
    float* __restrict__ g, float* __restrict__ cnt, int N)
{
    int lane = threadIdx.x & 31;     // feature group: 4 feats at lane*4
    int wrp  = threadIdx.x >> 5;     // 0..7, row stride 8
    int row0 = blockIdx.x * POOL_ROWS;
    if (row0 >= N) return;
    int row1 = min(row0 + POOL_ROWS, N);

    const uint2* av = reinterpret_cast<const uint2*>(a);   // row = 32 uint2

    float f0 = 0.f, f1 = 0.f, f2 = 0.f, f3 = 0.f, count = 0.f;
    int cur = -1;

    for (int r = row0 + wrp; r < row1; r += 8) {
        int b = __ldg(batch + r);
        if (b != cur) {
            if (cur >= 0) {
                atomicAdd(&g[cur * HID + lane * 4 + 0], f0);
                atomicAdd(&g[cur * HID + lane * 4 + 1], f1);
                atomicAdd(&g[cur * HID + lane * 4 + 2], f2);
                atomicAdd(&g[cur * HID + lane * 4 + 3], f3);
                if (lane == 0) atomicAdd(&cnt[cur], count);
            }
            f0 = f1 = f2 = f3 = 0.f; count = 0.f; cur = b;
        }
        uint2 u = av[(size_t)r * 32 + lane];
        float2 qa = __half22float2(*reinterpret_cast<__half2*>(&u.x));
        float2 qb = __half22float2(*reinterpret_cast<__half2*>(&u.y));
        f0 += qa.x; f1 += qa.y; f2 += qb.x; f3 += qb.y;
        count += 1.f;
    }
    if (cur >= 0) {
        atomicAdd(&g[cur * HID + lane * 4 + 0], f0);
        atomicAdd(&g[cur * HID + lane * 4 + 1], f1);
        atomicAdd(&g[cur * HID + lane * 4 + 2], f2);
        atomicAdd(&g[cur * HID + lane * 4 + 3], f3);
        if (lane == 0) atomicAdd(&cnt[cur], count);
    }
}

// ---------------- final MLP ----------------
__global__ void mlp_kernel(
    const float* __restrict__ g, const float* __restrict__ cnt,
    const float* __restrict__ Wc1, const float* __restrict__ bc1,
    const float* __restrict__ Wc2, const float* __restrict__ bc2,
    float* __restrict__ out)
{
    __shared__ float gr[HID], z[HID];
    int b = blockIdx.x;
    int t = threadIdx.x;
    float c = cnt[b];
    c = (c < 1.f) ? 1.f : c;
    gr[t] = g[b * HID + t] / c;
    __syncthreads();

    float acc = bc1[t];
    for (int k = 0; k < HID; k++) acc += gr[k] * Wc1[k * HID + t];
    z[t] = fmaxf(acc, 0.f);
    __syncthreads();

    if (t < NC) {
        float o = bc2[t];
        for (int k = 0; k < HID; k++) o += z[k] * Wc2[k * NC + t];
        out[b * NC + t] = o;
    }
}

// ---------------- launch ----------------
extern "C" void kernel_launch(void* const* d_in, const int* in_sizes, int n_in,
                              void* d_out, int out_size)
{
    const float* x    = (const float*)d_in[0];
    const int*   edge = (const int*)  d_in[1];
    const int*   batc = (const int*)  d_in[2];
    const float* W1   = (const float*)d_in[3];
    const float* b1   = (const float*)d_in[4];
    const float* W2   = (const float*)d_in[5];
    const float* b2   = (const float*)d_in[6];
    const float* Wc1  = (const float*)d_in[7];
    const float* bc1  = (const float*)d_in[8];
    const float* Wc2  = (const float*)d_in[9];
    const float* bc2  = (const float*)d_in[10];

    const int N = in_sizes[0] / HID;
    const int E = in_sizes[1] / 2;
    const int* src = edge;
    const int* dst = edge + E;

    int *degi_p, *rowptr_p, *cursor_p, *csr_p;
    float *dinv_p, *g_p, *cnt_p;
    __half *h_p, *ah_p;
    cudaGetSymbolAddress((void**)&degi_p,   g_degi);
    cudaGetSymbolAddress((void**)&rowptr_p, g_rowptr);
    cudaGetSymbolAddress((void**)&cursor_p, g_cursor);
    cudaGetSymbolAddress((void**)&csr_p,    g_csr);
    cudaGetSymbolAddress((void**)&dinv_p,   g_dinv);
    cudaGetSymbolAddress((void**)&h_p,      g_h);
    cudaGetSymbolAddress((void**)&ah_p,     g_ah);
    cudaGetSymbolAddress((void**)&g_p,      g_pool);
    cudaGetSymbolAddress((void**)&cnt_p,    g_cnt);

    const int SMEM = 2 * 128 * APAD * (int)sizeof(__half);
    cudaFuncSetAttribute(hgemm128<true>,  cudaFuncAttributeMaxDynamicSharedMemorySize, SMEM);
    cudaFuncSetAttribute(hgemm128<false>, cudaFuncAttributeMaxDynamicSharedMemorySize, SMEM);

    // ---- CSR build + normalization (unfused, proven) ----
    cudaMemsetAsync(degi_p, 0, N * sizeof(int));
    hist_kernel<<<(E + 255) / 256, 256>>>(dst, degi_p, E);
    scan_kernel<<<1, 1024>>>(degi_p, rowptr_p, N);
    cudaMemcpyAsync(cursor_p, rowptr_p, N * sizeof(int), cudaMemcpyDeviceToDevice);
    fill_kernel<<<(E + 255) / 256, 256>>>(src, dst, cursor_p, csr_p, E);
    dinv_kernel<<<(N + 255) / 256, 256>>>(degi_p, dinv_p, N);

    const int gemmGrid = (N + 127) / 128;
    const int aggGrid  = (N * 32 + 255) / 256;

    // ---- layer 1 ----
    hgemm128<true><<<gemmGrid, 256, SMEM>>>(x, W1, dinv_p, h_p, N);
    agg_kernel<<<aggGrid, 256>>>(h_p, csr_p, rowptr_p, dinv_p, b1, ah_p, N);

    // ---- layer 2 ----
    hgemm128<false><<<gemmGrid, 256, SMEM>>>(ah_p, W2, dinv_p, h_p, N);
    agg_kernel<<<aggGrid, 256>>>(h_p, csr_p, rowptr_p, dinv_p, b2, ah_p, N);

    // ---- pooling + MLP ----
    cudaMemsetAsync(g_p, 0, NG * HID * sizeof(float));
    cudaMemsetAsync(cnt_p, 0, NG * sizeof(float));
    pool_kernel<<<(N + POOL_ROWS - 1) / POOL_ROWS, 256>>>(ah_p, batc, g_p, cnt_p, N);
    mlp_kernel<<<NG, HID>>>(g_p, cnt_p, Wc1, bc1, Wc2, bc2, (float*)d_out);
}